// round 1
// baseline (speedup 1.0000x reference)
#include <cuda_runtime.h>
#include <math.h>

// Problem constants
#define S_LEN  2048
#define DMODEL 2048
#define HDIM   128
#define NH     16
#define NG     4
#define BATCH  2

// Attention tiling
#define BQ    128     // Q rows per block
#define BK    64      // K/V rows per chunk
#define QPAD  132     // padded row length (floats) for Q/K/V tiles -> conflict-free frag loads
#define PPAD  68      // padded row length for P tile
#define NTO   16      // HDIM/8 output n-tiles
#define NTS   8       // BK/8 score n-tiles

// Projection tiling
#define PB    128
#define PK    32
#define APAD  36

// Scratch for attention output [B*S, DMODEL] (pre-projection), fp32.
__device__ float g_attn[(size_t)BATCH * S_LEN * DMODEL];

__device__ __forceinline__ float f2tf(float x) {
    unsigned u;
    asm("cvt.rna.tf32.f32 %0, %1;" : "=r"(u) : "f"(x));
    return __uint_as_float(u);
}

__device__ __forceinline__ void mma_tf32(float c[4],
    unsigned a0, unsigned a1, unsigned a2, unsigned a3,
    unsigned b0, unsigned b1)
{
    asm volatile(
        "mma.sync.aligned.m16n8k8.row.col.f32.tf32.tf32.f32 "
        "{%0,%1,%2,%3}, {%4,%5,%6,%7}, {%8,%9}, {%0,%1,%2,%3};"
        : "+f"(c[0]), "+f"(c[1]), "+f"(c[2]), "+f"(c[3])
        : "r"(a0), "r"(a1), "r"(a2), "r"(a3), "r"(b0), "r"(b1));
}

// ---------------------------------------------------------------------------
// Flash attention, tf32 mma, online softmax.
// Grid: (S/BQ, NH, B). Block: 256 threads = 8 warps; warp w owns rows
// [w*16, w*16+16) of the Q tile.
// ---------------------------------------------------------------------------
__global__ __launch_bounds__(256, 1)
void attn_kernel(const float* __restrict__ q,
                 const float* __restrict__ k,
                 const float* __restrict__ v)
{
    extern __shared__ float sm[];
    float* Qs = sm;                    // BQ x QPAD
    float* Ks = Qs + BQ * QPAD;        // BK x QPAD
    float* Vs = Ks + BK * QPAD;        // BK x QPAD
    float* Ps = Vs + BK * QPAD;        // BQ x PPAD

    const int tid  = threadIdx.x;
    const int warp = tid >> 5;
    const int lane = tid & 31;
    const int gid  = lane >> 2;   // groupID (row within 8)
    const int tig  = lane & 3;    // thread in group (col)
    const int b  = blockIdx.z;
    const int h  = blockIdx.y;
    const int g  = h >> 2;        // group = head / HEADS_PER_GROUP
    const int s0 = blockIdx.x * BQ;
    const int wr = warp * 16;

    const float scale = 0.08838834764831845f;  // 1/sqrt(128)

    // Load Q tile (scaled, tf32-rounded)
    const float* qg = q + ((size_t)(b * S_LEN + s0)) * DMODEL + h * HDIM;
    for (int i = tid; i < BQ * (HDIM / 4); i += 256) {
        int r = i >> 5, c4 = (i & 31) << 2;
        float4 t = *(const float4*)(qg + (size_t)r * DMODEL + c4);
        float* d = Qs + r * QPAD + c4;
        d[0] = f2tf(t.x * scale); d[1] = f2tf(t.y * scale);
        d[2] = f2tf(t.z * scale); d[3] = f2tf(t.w * scale);
    }

    float Oc[NTO][4];
#pragma unroll
    for (int i = 0; i < NTO; i++) { Oc[i][0] = Oc[i][1] = Oc[i][2] = Oc[i][3] = 0.f; }
    float m0r = -1e30f, m1r = -1e30f, l0 = 0.f, l1 = 0.f;

    const float* kg = k + (size_t)(b * S_LEN) * (NG * HDIM) + g * HDIM;
    const float* vg = v + (size_t)(b * S_LEN) * (NG * HDIM) + g * HDIM;

    for (int jt = 0; jt < S_LEN / BK; jt++) {
        __syncthreads();   // previous iteration's tile reads complete
        const int kt0 = jt * BK;
        for (int i = tid; i < BK * (HDIM / 4); i += 256) {
            int r = i >> 5, c4 = (i & 31) << 2;
            float4 t = *(const float4*)(kg + (size_t)(kt0 + r) * (NG * HDIM) + c4);
            float* d = Ks + r * QPAD + c4;
            d[0] = f2tf(t.x); d[1] = f2tf(t.y); d[2] = f2tf(t.z); d[3] = f2tf(t.w);
            float4 u = *(const float4*)(vg + (size_t)(kt0 + r) * (NG * HDIM) + c4);
            float* e = Vs + r * QPAD + c4;
            e[0] = f2tf(u.x); e[1] = f2tf(u.y); e[2] = f2tf(u.z); e[3] = f2tf(u.w);
        }
        __syncthreads();   // tiles (and Q on first iter) ready

        // ---- scores = Q @ K^T  (warp: 16 x 64) ----
        float sc[NTS][4];
#pragma unroll
        for (int i = 0; i < NTS; i++) { sc[i][0] = sc[i][1] = sc[i][2] = sc[i][3] = 0.f; }

#pragma unroll
        for (int ks = 0; ks < HDIM / 8; ks++) {
            const int kc = ks * 8;
            unsigned a0 = __float_as_uint(Qs[(wr + gid)     * QPAD + kc + tig]);
            unsigned a1 = __float_as_uint(Qs[(wr + gid + 8) * QPAD + kc + tig]);
            unsigned a2 = __float_as_uint(Qs[(wr + gid)     * QPAD + kc + tig + 4]);
            unsigned a3 = __float_as_uint(Qs[(wr + gid + 8) * QPAD + kc + tig + 4]);
#pragma unroll
            for (int nt = 0; nt < NTS; nt++) {
                unsigned b0 = __float_as_uint(Ks[(nt * 8 + gid) * QPAD + kc + tig]);
                unsigned b1 = __float_as_uint(Ks[(nt * 8 + gid) * QPAD + kc + tig + 4]);
                mma_tf32(sc[nt], a0, a1, a2, a3, b0, b1);
            }
        }

        // ---- online softmax (rows wr+gid and wr+gid+8) ----
        float mx0 = -1e30f, mx1 = -1e30f;
#pragma unroll
        for (int nt = 0; nt < NTS; nt++) {
            mx0 = fmaxf(mx0, fmaxf(sc[nt][0], sc[nt][1]));
            mx1 = fmaxf(mx1, fmaxf(sc[nt][2], sc[nt][3]));
        }
        mx0 = fmaxf(mx0, __shfl_xor_sync(0xffffffffu, mx0, 1));
        mx0 = fmaxf(mx0, __shfl_xor_sync(0xffffffffu, mx0, 2));
        mx1 = fmaxf(mx1, __shfl_xor_sync(0xffffffffu, mx1, 1));
        mx1 = fmaxf(mx1, __shfl_xor_sync(0xffffffffu, mx1, 2));
        const float mn0 = fmaxf(m0r, mx0), mn1 = fmaxf(m1r, mx1);
        const float al0 = __expf(m0r - mn0), al1 = __expf(m1r - mn1);
        m0r = mn0; m1r = mn1;

        float s0s = 0.f, s1s = 0.f;
#pragma unroll
        for (int nt = 0; nt < NTS; nt++) {
            float p0 = __expf(sc[nt][0] - mn0);
            float p1 = __expf(sc[nt][1] - mn0);
            float p2 = __expf(sc[nt][2] - mn1);
            float p3 = __expf(sc[nt][3] - mn1);
            s0s += p0 + p1; s1s += p2 + p3;
            Ps[(wr + gid)     * PPAD + nt * 8 + 2 * tig]     = f2tf(p0);
            Ps[(wr + gid)     * PPAD + nt * 8 + 2 * tig + 1] = f2tf(p1);
            Ps[(wr + gid + 8) * PPAD + nt * 8 + 2 * tig]     = f2tf(p2);
            Ps[(wr + gid + 8) * PPAD + nt * 8 + 2 * tig + 1] = f2tf(p3);
        }
        s0s += __shfl_xor_sync(0xffffffffu, s0s, 1);
        s0s += __shfl_xor_sync(0xffffffffu, s0s, 2);
        s1s += __shfl_xor_sync(0xffffffffu, s1s, 1);
        s1s += __shfl_xor_sync(0xffffffffu, s1s, 2);
        l0 = l0 * al0 + s0s;
        l1 = l1 * al1 + s1s;

#pragma unroll
        for (int nt = 0; nt < NTO; nt++) {
            Oc[nt][0] *= al0; Oc[nt][1] *= al0;
            Oc[nt][2] *= al1; Oc[nt][3] *= al1;
        }
        __syncwarp();   // Ps rows are warp-private; make writes visible

        // ---- O += P @ V  (warp: 16 x 128) ----
#pragma unroll
        for (int ks = 0; ks < BK / 8; ks++) {
            const int kc = ks * 8;
            unsigned a0 = __float_as_uint(Ps[(wr + gid)     * PPAD + kc + tig]);
            unsigned a1 = __float_as_uint(Ps[(wr + gid + 8) * PPAD + kc + tig]);
            unsigned a2 = __float_as_uint(Ps[(wr + gid)     * PPAD + kc + tig + 4]);
            unsigned a3 = __float_as_uint(Ps[(wr + gid + 8) * PPAD + kc + tig + 4]);
#pragma unroll
            for (int nt = 0; nt < NTO; nt++) {
                unsigned b0 = __float_as_uint(Vs[(kc + tig)     * QPAD + nt * 8 + gid]);
                unsigned b1 = __float_as_uint(Vs[(kc + tig + 4) * QPAD + nt * 8 + gid]);
                mma_tf32(Oc[nt], a0, a1, a2, a3, b0, b1);
            }
        }
    }

    // Epilogue: normalize and write to scratch
    const float il0 = 1.f / l0, il1 = 1.f / l1;
    float* og = g_attn + (size_t)(b * S_LEN + s0) * DMODEL + h * HDIM;
#pragma unroll
    for (int nt = 0; nt < NTO; nt++) {
        const int col = nt * 8 + 2 * tig;
        og[(size_t)(wr + gid)     * DMODEL + col]     = Oc[nt][0] * il0;
        og[(size_t)(wr + gid)     * DMODEL + col + 1] = Oc[nt][1] * il0;
        og[(size_t)(wr + gid + 8) * DMODEL + col]     = Oc[nt][2] * il1;
        og[(size_t)(wr + gid + 8) * DMODEL + col + 1] = Oc[nt][3] * il1;
    }
}

// ---------------------------------------------------------------------------
// Projection: out[m][n] = sum_k attn[m][k] * Wc[n][k] + bc[n]
// Grid: (DMODEL/PB, (B*S)/PB). Block: 256 threads = 8 warps.
// ---------------------------------------------------------------------------
__global__ __launch_bounds__(256, 2)
void proj_kernel(const float* __restrict__ Wc,
                 const float* __restrict__ bc,
                 float* __restrict__ out)
{
    __shared__ float As[PB * APAD];
    __shared__ float Bs[PB * APAD];

    const int tid  = threadIdx.x;
    const int warp = tid >> 5;
    const int lane = tid & 31;
    const int gid  = lane >> 2;
    const int tig  = lane & 3;
    const int n0 = blockIdx.x * PB;
    const int m0 = blockIdx.y * PB;
    const int wr = warp * 16;

    float acc[16][4];
#pragma unroll
    for (int i = 0; i < 16; i++) { acc[i][0] = acc[i][1] = acc[i][2] = acc[i][3] = 0.f; }

    for (int kc = 0; kc < DMODEL; kc += PK) {
        __syncthreads();
        for (int i = tid; i < PB * (PK / 4); i += 256) {
            int r = i >> 3, c4 = (i & 7) << 2;
            float4 t = *(const float4*)(g_attn + (size_t)(m0 + r) * DMODEL + kc + c4);
            float* d = As + r * APAD + c4;
            d[0] = f2tf(t.x); d[1] = f2tf(t.y); d[2] = f2tf(t.z); d[3] = f2tf(t.w);
            float4 u = *(const float4*)(Wc + (size_t)(n0 + r) * DMODEL + kc + c4);
            float* e = Bs + r * APAD + c4;
            e[0] = f2tf(u.x); e[1] = f2tf(u.y); e[2] = f2tf(u.z); e[3] = f2tf(u.w);
        }
        __syncthreads();

#pragma unroll
        for (int ks = 0; ks < PK / 8; ks++) {
            const int kk = ks * 8;
            unsigned a0 = __float_as_uint(As[(wr + gid)     * APAD + kk + tig]);
            unsigned a1 = __float_as_uint(As[(wr + gid + 8) * APAD + kk + tig]);
            unsigned a2 = __float_as_uint(As[(wr + gid)     * APAD + kk + tig + 4]);
            unsigned a3 = __float_as_uint(As[(wr + gid + 8) * APAD + kk + tig + 4]);
#pragma unroll
            for (int nt = 0; nt < 16; nt++) {
                unsigned b0 = __float_as_uint(Bs[(nt * 8 + gid) * APAD + kk + tig]);
                unsigned b1 = __float_as_uint(Bs[(nt * 8 + gid) * APAD + kk + tig + 4]);
                mma_tf32(acc[nt], a0, a1, a2, a3, b0, b1);
            }
        }
    }

#pragma unroll
    for (int nt = 0; nt < 16; nt++) {
        const int col = n0 + nt * 8 + 2 * tig;
        const float b0v = bc[col], b1v = bc[col + 1];
        out[(size_t)(m0 + wr + gid)     * DMODEL + col]     = acc[nt][0] + b0v;
        out[(size_t)(m0 + wr + gid)     * DMODEL + col + 1] = acc[nt][1] + b1v;
        out[(size_t)(m0 + wr + gid + 8) * DMODEL + col]     = acc[nt][2] + b0v;
        out[(size_t)(m0 + wr + gid + 8) * DMODEL + col + 1] = acc[nt][3] + b1v;
    }
}

// ---------------------------------------------------------------------------
extern "C" void kernel_launch(void* const* d_in, const int* in_sizes, int n_in,
                              void* d_out, int out_size)
{
    const float* q  = (const float*)d_in[0];
    const float* k  = (const float*)d_in[1];
    const float* v  = (const float*)d_in[2];
    const float* Wc = (const float*)d_in[3];
    const float* bc = (const float*)d_in[4];
    float* out = (float*)d_out;

    const int attn_smem = (BQ * QPAD + 2 * BK * QPAD + BQ * PPAD) * (int)sizeof(float);
    cudaFuncSetAttribute(attn_kernel, cudaFuncAttributeMaxDynamicSharedMemorySize, attn_smem);

    dim3 agrid(S_LEN / BQ, NH, BATCH);
    attn_kernel<<<agrid, 256, attn_smem>>>(q, k, v);

    dim3 pgrid(DMODEL / PB, (BATCH * S_LEN) / PB);
    proj_kernel<<<pgrid, 256>>>(Wc, bc, out);
}